// round 7
// baseline (speedup 1.0000x reference)
#include <cuda_runtime.h>
#include <cstdint>

#define NUM_CLASSES 17929
#define BATCH       512
#define NUM_MODELS  16
#define HIDDEN      4

#define TILE_C      256            // classes per CTA (== TPB)
#define TPB         256
#define BT          2              // batch rows per tile
#define RPC         128            // batch rows per CTA  (grid.y = 4)
#define NT          (RPC / BT)     // 64 tiles per CTA
#define STAGES      3
#define PLANES      (NUM_MODELS * BT)            // 32
#define PADW        264                          // 256 + shift(<=3) + pad
#define STAGE_FLOATS (PLANES * PADW)             // 8448
#define STAGE_BYTES  (STAGE_FLOATS * 4)          // 33792
#define SMEM_BYTES   (STAGES * STAGE_BYTES)      // 101376 -> 2 CTAs/SM

__device__ __forceinline__ void cp_async16(uint32_t dst, const float* src) {
    asm volatile("cp.async.cg.shared.global [%0], [%1], 16;\n" :: "r"(dst), "l"(src));
}
__device__ __forceinline__ void cp_async4(uint32_t dst, const float* src) {
    asm volatile("cp.async.ca.shared.global [%0], [%1], 4;\n" :: "r"(dst), "l"(src));
}
__device__ __forceinline__ void cp_commit() {
    asm volatile("cp.async.commit_group;\n" ::: "memory");
}
__device__ __forceinline__ void cp_wait1() {
    asm volatile("cp.async.wait_group 1;\n" ::: "memory");
}
__device__ __forceinline__ void cp_wait0() {
    asm volatile("cp.async.wait_group 0;\n" ::: "memory");
}

extern __shared__ float smem[];    // [STAGES][PLANES][PADW]

__global__ void __launch_bounds__(TPB, 2)
family_mlp_kernel(const float* __restrict__ x,     // [M, B, C]
                  const float* __restrict__ W1,    // [C, H, M]
                  const float* __restrict__ b1,    // [C, H]
                  const float* __restrict__ W2,    // [C, H]
                  const float* __restrict__ b2,    // [C]
                  float* __restrict__ out)         // [B, C]
{
    const int tid = threadIdx.x;
    int c0 = blockIdx.x * TILE_C;
    if (c0 > NUM_CLASSES - TILE_C) c0 = NUM_CLASSES - TILE_C;   // overlap last block
    const int c04 = c0 & 3;
    const int c   = c0 + tid;
    const int r0  = blockIdx.y * RPC;

    // ---- per-class weights in registers ----
    float w1[HIDDEN][NUM_MODELS];
    {
        const float4* wv = reinterpret_cast<const float4*>(W1) + (size_t)c * 16;
        #pragma unroll
        for (int k = 0; k < 16; ++k) {
            float4 v = __ldg(wv + k);
            const int h = k >> 2, mm = (k & 3) * 4;
            w1[h][mm + 0] = v.x; w1[h][mm + 1] = v.y;
            w1[h][mm + 2] = v.z; w1[h][mm + 3] = v.w;
        }
    }
    const float4 bb1 = __ldg(reinterpret_cast<const float4*>(b1) + c);
    const float4 ww2 = __ldg(reinterpret_cast<const float4*>(W2) + c);
    const float  bb2 = __ldg(b2 + c);

    const size_t plane = (size_t)BATCH * NUM_CLASSES;
    float* obase = out + (size_t)r0 * NUM_CLASSES + c;

    uint32_t sbase;
    asm("{ .reg .u64 t; cvta.to.shared.u64 t, %1; cvt.u32.u64 %0, t; }"
        : "=r"(sbase) : "l"(smem));

    const int lane64 = tid & 63;    // position within a plane's 64 float4 copies
    const int pgrp   = tid >> 6;    // 0..3: plane group

    // issue one tile's copies: 32 planes x 64 float4 (+ <=3 tail scalars/plane)
    auto issue_tile = [&](int t) {
        const int stage = t % STAGES;
        const uint32_t s0 = sbase + stage * STAGE_BYTES;
        #pragma unroll
        for (int it = 0; it < PLANES / 4; ++it) {
            const int q = pgrp + (it << 2);         // 0..31
            const int m = q >> 1, b = q & 1;
            const int a = (c04 + 2 * t + b) & 3;    // misalignment in elements
            const float* g = x + (size_t)m * plane
                               + (size_t)(r0 + 2 * t + b) * NUM_CLASSES + c0;
            const uint32_t dplane = s0 + q * (PADW * 4);
            cp_async16(dplane + lane64 * 16, (g - a) + lane64 * 4);
            if (lane64 < a)   // tail classes c0+256-a .. c0+255 -> slots 256..256+a-1
                cp_async4(dplane + (TILE_C + lane64) * 4, g + TILE_C - a + lane64);
        }
        cp_commit();
    };

    // ---- prologue ----
    issue_tile(0);
    issue_tile(1);

    #pragma unroll 1
    for (int t = 0; t < NT; ++t) {
        if (t == NT - 1) cp_wait0(); else cp_wait1();
        __syncthreads();   // (a) others' copies of tile t visible
                           // (b) all finished compute t-1 -> safe to overwrite its stage
        if (t + STAGES - 1 < NT) issue_tile(t + STAGES - 1);

        const int stage = t % STAGES;
        const float* sb = smem + stage * STAGE_FLOATS;

        #pragma unroll
        for (int b = 0; b < BT; ++b) {
            const int a = (c04 + 2 * t + b) & 3;
            const float* buf = sb + b * PADW + tid + a;   // m-plane stride 2*PADW

            float h0 = bb1.x, h1 = bb1.y, h2 = bb1.z, h3 = bb1.w;
            #pragma unroll
            for (int m = 0; m < NUM_MODELS; ++m) {
                const float v = buf[m * (2 * PADW)];
                h0 = fmaf(v, w1[0][m], h0);
                h1 = fmaf(v, w1[1][m], h1);
                h2 = fmaf(v, w1[2][m], h2);
                h3 = fmaf(v, w1[3][m], h3);
            }
            float acc = bb2;
            acc = fmaf(fmaxf(h0, 0.0f), ww2.x, acc);
            acc = fmaf(fmaxf(h1, 0.0f), ww2.y, acc);
            acc = fmaf(fmaxf(h2, 0.0f), ww2.z, acc);
            acc = fmaf(fmaxf(h3, 0.0f), ww2.w, acc);
            __stcs(obase + (size_t)(2 * t + b) * NUM_CLASSES, acc);
        }
    }
}

extern "C" void kernel_launch(void* const* d_in, const int* in_sizes, int n_in,
                              void* d_out, int out_size)
{
    const float* x  = (const float*)d_in[0];   // [16, 512, 17929]
    const float* W1 = (const float*)d_in[1];   // [17929, 4, 16]
    const float* b1 = (const float*)d_in[2];   // [17929, 4]
    const float* W2 = (const float*)d_in[3];   // [17929, 4]
    const float* b2 = (const float*)d_in[4];   // [17929]
    float* out = (float*)d_out;                // [512, 17929]

    cudaFuncSetAttribute(family_mlp_kernel,
                         cudaFuncAttributeMaxDynamicSharedMemorySize, SMEM_BYTES);

    dim3 grid((NUM_CLASSES + TILE_C - 1) / TILE_C, BATCH / RPC);   // 71 x 4 = 284 CTAs
    family_mlp_kernel<<<grid, TPB, SMEM_BYTES>>>(x, W1, b1, W2, b2, out);
}